// round 5
// baseline (speedup 1.0000x reference)
#include <cuda_runtime.h>

// out[r] = dot(W1[i1[r]], W2[i2[r]]) + b1[i1[r]] + b2[i2[r]]
// 16 lanes/row, one 256-bit load per table per lane (LDG.256),
// 128-thread blocks for fine-grained SM balance (2048 blocks, single wave).

#define BATCH 16384
#define EMBED 128

struct F8 { float v[8]; };

__device__ __forceinline__ F8 ldg256(const float* p) {
    F8 r;
    asm volatile(
        "ld.global.nc.L2::evict_last.v8.f32 {%0,%1,%2,%3,%4,%5,%6,%7}, [%8];"
        : "=f"(r.v[0]), "=f"(r.v[1]), "=f"(r.v[2]), "=f"(r.v[3]),
          "=f"(r.v[4]), "=f"(r.v[5]), "=f"(r.v[6]), "=f"(r.v[7])
        : "l"(p));
    return r;
}

__global__ __launch_bounds__(128)
void fused_embed_dot_kernel(const int* __restrict__ i1,
                            const int* __restrict__ i2,
                            const float* __restrict__ W1,
                            const float* __restrict__ W2,
                            const float* __restrict__ b1,
                            const float* __restrict__ b2,
                            float* __restrict__ out) {
    int t   = blockIdx.x * blockDim.x + threadIdx.x;
    int row = t >> 4;       // 16 threads per row
    int sub = t & 15;       // 0..15, each covers 8 floats (32B)

    int idx1 = __ldg(&i1[row]);
    int idx2 = __ldg(&i2[row]);

    // Bias gathers issued early; overlap with row gathers.
    float bv1 = __ldg(&b1[idx1]);
    float bv2 = __ldg(&b2[idx2]);

    const float* r1 = W1 + idx1 * EMBED + sub * 8;
    const float* r2 = W2 + idx2 * EMBED + sub * 8;

    // Two independent 256-bit loads per lane.
    F8 a = ldg256(r1);
    F8 c = ldg256(r2);

    float acc0 = a.v[0] * c.v[0];
    float acc1 = a.v[1] * c.v[1];
    acc0 = fmaf(a.v[2], c.v[2], acc0);
    acc1 = fmaf(a.v[3], c.v[3], acc1);
    acc0 = fmaf(a.v[4], c.v[4], acc0);
    acc1 = fmaf(a.v[5], c.v[5], acc1);
    acc0 = fmaf(a.v[6], c.v[6], acc0);
    acc1 = fmaf(a.v[7], c.v[7], acc1);
    float acc = acc0 + acc1;

    // Reduce over the 16-lane group.
    acc += __shfl_xor_sync(0xFFFFFFFFu, acc, 1);
    acc += __shfl_xor_sync(0xFFFFFFFFu, acc, 2);
    acc += __shfl_xor_sync(0xFFFFFFFFu, acc, 4);
    acc += __shfl_xor_sync(0xFFFFFFFFu, acc, 8);

    if (sub == 0)
        out[row] = acc + bv1 + bv2;
}

extern "C" void kernel_launch(void* const* d_in, const int* in_sizes, int n_in,
                              void* d_out, int out_size) {
    const int*   i1 = (const int*)d_in[0];
    const int*   i2 = (const int*)d_in[1];
    const float* W1 = (const float*)d_in[2];
    const float* W2 = (const float*)d_in[3];
    const float* b1 = (const float*)d_in[4];
    const float* b2 = (const float*)d_in[5];
    float* out = (float*)d_out;

    // 16384 rows * 16 threads / 128 = 2048 blocks (13.8/SM, fine balance)
    fused_embed_dot_kernel<<<(BATCH * 16) / 128, 128>>>(i1, i2, W1, W2, b1, b2, out);
}